// round 17
// baseline (speedup 1.0000x reference)
#include <cuda_runtime.h>
#include <cuda_fp16.h>
#include <math.h>
#include <stdint.h>

#define S_ 196
#define B_ 64
#define E_ 1024
#define D_ 1800
#define W_ 512
#define V_ 32000
#define WE_ (W_ + E_)       // 1536
#define DE_ (D_ + E_)       // 2824
#define DWE_ (D_ + W_ + E_) // 3336

// ---------------------------------------------------------------------------
// Scratch
// ---------------------------------------------------------------------------
struct Scratch {
    float havg[B_ * E_];
    float skpA[2][6][B_ * D_];
    float skpB[2][6][B_ * D_];
    float qpart[B_ * D_];
    float spart[3 * S_ * B_];
    float beta[B_];
    float ctx[B_ * E_];
    float x[B_ * WE_];
    float z[B_ * DWE_];
    float gp0[4][B_ * 4 * D_];
    float gp1[4][B_ * 4 * D_];
    float lgp[3][B_ * V_];
    int   amax[B_];
    __half h16[S_ * B_ * E_];
    __half w16[D_ * E_];
};
__device__ Scratch g_s;

// ---------------------------------------------------------------------------
// fp16 MMA helpers
// ---------------------------------------------------------------------------
__device__ __forceinline__ uint32_t packh2(float a, float b) {
    __half2 h = __floats2half2_rn(a, b);
    return *(uint32_t*)&h;
}
__device__ __forceinline__ void mma_f16(float (&c)[4], const uint32_t (&a)[4],
                                        const uint32_t b0, const uint32_t b1) {
    asm volatile(
        "mma.sync.aligned.m16n8k16.row.col.f32.f16.f16.f32 "
        "{%0,%1,%2,%3},{%4,%5,%6,%7},{%8,%9},{%0,%1,%2,%3};"
        : "+f"(c[0]), "+f"(c[1]), "+f"(c[2]), "+f"(c[3])
        : "r"(a[0]), "r"(a[1]), "r"(a[2]), "r"(a[3]), "r"(b0), "r"(b1));
}
__device__ __forceinline__ void ldsm4(uint32_t (&r)[4], uint32_t addr) {
    asm volatile("ldmatrix.sync.aligned.m8n8.x4.shared.b16 {%0,%1,%2,%3}, [%4];"
        : "=r"(r[0]), "=r"(r[1]), "=r"(r[2]), "=r"(r[3]) : "r"(addr));
}
__device__ __forceinline__ void ldsm4p(uint32_t* r, uint32_t addr) {
    asm volatile("ldmatrix.sync.aligned.m8n8.x4.shared.b16 {%0,%1,%2,%3}, [%4];"
        : "=r"(r[0]), "=r"(r[1]), "=r"(r[2]), "=r"(r[3]) : "r"(addr));
}
__device__ __forceinline__ void ldsm2(uint32_t (&r)[2], uint32_t addr) {
    asm volatile("ldmatrix.sync.aligned.m8n8.x2.shared.b16 {%0,%1}, [%2];"
        : "=r"(r[0]), "=r"(r[1]) : "r"(addr));
}
__device__ __forceinline__ void ld8(float* d, const float* p) {
    float4 a = ((const float4*)p)[0], b = ((const float4*)p)[1];
    d[0]=a.x; d[1]=a.y; d[2]=a.z; d[3]=a.w; d[4]=b.x; d[5]=b.y; d[6]=b.z; d[7]=b.w;
}
__device__ __forceinline__ void add8(float* d, const float* p) {
    float4 a = ((const float4*)p)[0], b = ((const float4*)p)[1];
    d[0]+=a.x; d[1]+=a.y; d[2]+=a.z; d[3]+=a.w; d[4]+=b.x; d[5]+=b.y; d[6]+=b.z; d[7]+=b.w;
}
__device__ __forceinline__ void cpa16(uint32_t dst, const void* src, int sz) {
    asm volatile("cp.async.cg.shared.global [%0], [%1], 16, %2;"
        :: "r"(dst), "l"(src), "r"(sz) : "memory");
}
#define CPA_COMMIT() asm volatile("cp.async.commit_group;" ::: "memory")
#define CPA_WAIT2()  asm volatile("cp.async.wait_group 2;" ::: "memory")

#define SPADH 36

// ---------------------------------------------------------------------------
// fp32 -> fp16 preconversion
// ---------------------------------------------------------------------------
__global__ __launch_bounds__(256) void conv16_kernel(
    const float* __restrict__ h, const float* __restrict__ Wa1,
    __half* __restrict__ h16, __half* __restrict__ w16)
{
    const int HT = S_ * B_ * E_ / 8;
    const int WT = D_ * E_ / 8;
    int idx = blockIdx.x * 256 + threadIdx.x;
    if (idx < HT) {
        const float4* p = (const float4*)(h + (size_t)idx * 8);
        float4 a = p[0], b = p[1];
        *(uint4*)(h16 + (size_t)idx * 8) =
            make_uint4(packh2(a.x, a.y), packh2(a.z, a.w),
                       packh2(b.x, b.y), packh2(b.z, b.w));
    } else if (idx - HT < WT) {
        int j = idx - HT;
        int n = j / (E_ / 8), k8 = j % (E_ / 8);
        const float4* p = (const float4*)(Wa1 + (size_t)n * DE_ + D_ + k8 * 8);
        float4 a = p[0], b = p[1];
        *(uint4*)(w16 + (size_t)n * E_ + k8 * 8) =
            make_uint4(packh2(a.x, a.y), packh2(a.z, a.w),
                       packh2(b.x, b.y), packh2(b.z, b.w));
    }
}

// ---------------------------------------------------------------------------
// Small-GEMM K-segment, fp16 MMA, ktile=64.
// A side sums nA contiguous partial slices (stride B_*K) + optional k-bias/relu.
// ---------------------------------------------------------------------------
struct SKJob {
    const float* A; int nA;
    const float* kb; int krelu;
    const float* W; int K; int ldw; int N; float* Cpart;
};
struct SKJob2 { SKJob j[2]; };

template<int BN>
__device__ __forceinline__ void seg64(
    const SKJob& j, const int nb, const int t0, const int t1,
    uint32_t As[64][SPADH], uint32_t Ws[BN][SPADH],
    float (&acc)[2][BN / 32][4])
{
    constexpr int NF  = BN / 32;
    constexpr int WFT = (BN == 64) ? 16 : 32;
    const int tid  = threadIdx.x;
    const int lane = tid & 31, wid = tid >> 5;
    const int warpM = wid >> 2, warpN = wid & 3;

    const int am  = tid & 63, akg = (tid >> 6) * 16;
    const int wn  = (BN == 64) ? (tid & 63) : (tid & 127);
    const int wkg = (BN == 64) ? ((tid >> 6) * 16) : ((tid >> 7) * 32);
    const bool wvalid = (nb + wn) < j.N;
    const int K = j.K;
    const size_t ASTRIDE = (size_t)B_ * K;
    const float* Arow = j.A + (size_t)am * K;
    const float* Wbase = j.W + (size_t)(nb + wn) * j.ldw;

    uint32_t aAddr[2][4], bAddr[NF][2];
    #pragma unroll
    for (int mf = 0; mf < 2; mf++)
        #pragma unroll
        for (int ks = 0; ks < 4; ks++)
            aAddr[mf][ks] = (uint32_t)__cvta_generic_to_shared(
                &As[warpM * 32 + mf * 16 + (lane & 15)][ks * 8 + 4 * (lane >> 4)]);
    #pragma unroll
    for (int nf = 0; nf < NF; nf++)
        #pragma unroll
        for (int hh = 0; hh < 2; hh++)
            bAddr[nf][hh] = (uint32_t)__cvta_generic_to_shared(
                &Ws[warpN * (BN / 4) + nf * 8 + (lane & 7)][hh * 16 + 4 * (lane >> 3)]);

    float ra[16], rw[WFT];

    auto loadA = [&](int ti) {
        #pragma unroll
        for (int g = 0; g < 2; g++) {
            const int k0 = ti * 64 + akg + g * 8;
            float* d = ra + g * 8;
            if (k0 + 8 <= K) {
                ld8(d, Arow + k0);
                for (int p = 1; p < j.nA; p++) add8(d, Arow + p * ASTRIDE + k0);
                if (j.kb) add8(d, j.kb + k0);
            } else {
                #pragma unroll
                for (int i = 0; i < 8; i++) {
                    int k = k0 + i; float v = 0.f;
                    if (k < K) {
                        v = Arow[k];
                        for (int p = 1; p < j.nA; p++) v += Arow[p * ASTRIDE + k];
                        if (j.kb) v += j.kb[k];
                    }
                    d[i] = v;
                }
            }
        }
        if (j.krelu) {
            #pragma unroll
            for (int i = 0; i < 16; i++) ra[i] = fmaxf(ra[i], 0.f);
        }
    };
    auto loadW = [&](int ti) {
        #pragma unroll
        for (int g = 0; g < WFT / 8; g++) {
            const int k0 = ti * 64 + wkg + g * 8;
            float* d = rw + g * 8;
            if (wvalid && k0 + 8 <= K) {
                ld8(d, Wbase + k0);
            } else {
                #pragma unroll
                for (int i = 0; i < 8; i++)
                    d[i] = (wvalid && (k0 + i) < K) ? Wbase[k0 + i] : 0.f;
            }
        }
    };

    loadA(t0);
    loadW(t0);

    for (int ti = t0; ti < t1; ti++) {
        __syncthreads();
        {
            uint4* p = (uint4*)&As[am][akg >> 1];
            p[0] = make_uint4(packh2(ra[0], ra[1]), packh2(ra[2], ra[3]),
                              packh2(ra[4], ra[5]), packh2(ra[6], ra[7]));
            p[1] = make_uint4(packh2(ra[8], ra[9]), packh2(ra[10], ra[11]),
                              packh2(ra[12], ra[13]), packh2(ra[14], ra[15]));
        }
        #pragma unroll
        for (int g = 0; g < WFT / 8; g++) {
            const float* r = rw + g * 8;
            *(uint4*)&Ws[wn][(wkg >> 1) + g * 4] =
                make_uint4(packh2(r[0], r[1]), packh2(r[2], r[3]),
                           packh2(r[4], r[5]), packh2(r[6], r[7]));
        }
        __syncthreads();

        if (ti + 1 < t1) { loadA(ti + 1); loadW(ti + 1); }

        uint32_t b[NF][8];
        #pragma unroll
        for (int nf = 0; nf < NF; nf++) {
            ldsm4p(&b[nf][0], bAddr[nf][0]);
            ldsm4p(&b[nf][4], bAddr[nf][1]);
        }
        #pragma unroll
        for (int ks = 0; ks < 4; ks++) {
            uint32_t a[2][4];
            ldsm4(a[0], aAddr[0][ks]);
            ldsm4(a[1], aAddr[1][ks]);
            #pragma unroll
            for (int nf = 0; nf < NF; nf++) {
                mma_f16(acc[0][nf], a[0], b[nf][2 * ks], b[nf][2 * ks + 1]);
                mma_f16(acc[1][nf], a[1], b[nf][2 * ks], b[nf][2 * ks + 1]);
            }
        }
    }
}

template<int BN>
__global__ __launch_bounds__(256) void sk_gemm_kernel(SKJob2 jobs)
{
    constexpr int NF = BN / 32;
    __shared__ __align__(16) uint32_t As[64][SPADH];
    __shared__ __align__(16) uint32_t Ws[BN][SPADH];

    const SKJob j = jobs.j[blockIdx.y];
    const int nb = blockIdx.x * BN;
    if (nb >= j.N) return;

    const int tiles = (j.K + 63) >> 6;
    const int KS = gridDim.z, kz = blockIdx.z;
    const int tpk = (tiles + KS - 1) / KS;
    const int t0 = kz * tpk;
    const int t1 = (t0 + tpk < tiles) ? (t0 + tpk) : tiles;

    float acc[2][NF][4] = {};
    if (t0 < t1)
        seg64<BN>(j, nb, t0, t1, As, Ws, acc);

    float* C = j.Cpart + (size_t)kz * 64 * j.N;
    const int tid = threadIdx.x, lane = tid & 31, wid = tid >> 5;
    const int warpM = wid >> 2, warpN = wid & 3;
    const int g = lane >> 2, t = lane & 3;

    #pragma unroll
    for (int mf = 0; mf < 2; mf++) {
        const int row = warpM * 32 + mf * 16 + g;
        #pragma unroll
        for (int nf = 0; nf < NF; nf++) {
            const int col = nb + warpN * (BN / 4) + nf * 8 + 2 * t;
            if (col < j.N) {
                *(float2*)&C[(size_t)row * j.N + col]       = make_float2(acc[mf][nf][0], acc[mf][nf][1]);
                *(float2*)&C[(size_t)(row + 8) * j.N + col] = make_float2(acc[mf][nf][2], acc[mf][nf][3]);
            }
        }
    }
}

// generic partial reduce: NP slices (stride total) + bias -> outp
template<int NP>
__global__ __launch_bounds__(256) void reduceN_kernel(
    const float* __restrict__ part, const float* __restrict__ bias,
    float* __restrict__ outp, int N, int total)
{
    int idx = blockIdx.x * 256 + threadIdx.x;
    if (idx >= total) return;
    int n = idx % N;
    float v = bias[n];
    #pragma unroll
    for (int p = 0; p < NP; p++) v += part[(size_t)p * total + idx];
    outp[idx] = v;
}

// ---------------------------------------------------------------------------
// Fused attention scores v3 (unchanged from R16)
// ---------------------------------------------------------------------------
#define SCS 20
#define A_STW (128 * SCS)
#define W_STW (128 * SCS)
#define NSTG 4
#define SC_DYN ((NSTG * (A_STW + W_STW)) * 4)

__global__ __launch_bounds__(256, 2) void mma_scores_kernel(
    const __half* __restrict__ h16, const __half* __restrict__ w16,
    const float* __restrict__ qpart, const float* __restrict__ Wa2,
    float* __restrict__ spart)
{
    extern __shared__ __align__(16) uint32_t dyn[];
    uint32_t* Asm = dyn;
    uint32_t* Wsm = dyn + NSTG * A_STW;

    const int tid = threadIdx.x, lane = tid & 31, wid = tid >> 5;
    const int warpM = wid >> 1, warpN = wid & 1;
    const int gq = lane >> 2, t = lane & 3;

    const int lrow = tid >> 1;
    const int lh   = tid & 1;
    const __half* Ag = h16 + ((size_t)blockIdx.x * 128 + lrow) * E_ + lh * 16;
    const int tile0 = blockIdx.y * 5;

    const uint32_t aDst = (uint32_t)__cvta_generic_to_shared(&Asm[lrow * SCS + lh * 8]);
    const uint32_t wDst = (uint32_t)__cvta_generic_to_shared(&Wsm[lrow * SCS + lh * 8]);

    uint32_t aA[2], bA[8];
    #pragma unroll
    for (int mf = 0; mf < 2; mf++)
        aA[mf] = (uint32_t)__cvta_generic_to_shared(
            &Asm[(warpM * 32 + mf * 16 + (lane & 15)) * SCS + 4 * (lane >> 4)]);
    #pragma unroll
    for (int nf = 0; nf < 8; nf++)
        bA[nf] = (uint32_t)__cvta_generic_to_shared(
            &Wsm[(warpN * 64 + nf * 8 + (lane & 7)) * SCS + 4 * ((lane >> 3) & 1)]);

    auto issue = [&](int st) {
        const int tile = st >> 5, kk = st & 31;
        const int slot = st & 3;
        const __half* asrc = Ag + kk * 32;
        const uint32_t ad = aDst + (uint32_t)slot * (A_STW * 4);
        cpa16(ad,      asrc,     16);
        cpa16(ad + 16, asrc + 8, 16);
        const int wr = (tile0 + tile) * 128 + lrow;
        const bool wv = wr < D_;
        const __half* wsrc = wv ? (w16 + (size_t)wr * E_ + kk * 32 + lh * 16) : w16;
        const int sz = wv ? 16 : 0;
        const uint32_t wd = wDst + (uint32_t)slot * (W_STW * 4);
        cpa16(wd,      wsrc,     sz);
        cpa16(wd + 16, wsrc + 8, sz);
    };

    float sacc[2][2] = {};
    float acc[2][8][4] = {};

    issue(0); CPA_COMMIT();
    issue(1); CPA_COMMIT();
    issue(2); CPA_COMMIT();

    for (int it = 0; it < 160; it++) {
        CPA_WAIT2();
        __syncthreads();
        if (it + 3 < 160) issue(it + 3);
        CPA_COMMIT();

        const uint32_t ao = (uint32_t)(it & 3) * (A_STW * 4);
        const uint32_t wo = (uint32_t)(it & 3) * (W_STW * 4);
        #pragma unroll
        for (int ks = 0; ks < 2; ks++) {
            uint32_t b[8][2];
            #pragma unroll
            for (int nf = 0; nf < 8; nf++) ldsm2(b[nf], bA[nf] + wo + ks * 32);
            #pragma unroll
            for (int mf = 0; mf < 2; mf++) {
                uint32_t a[4];
                ldsm4(a, aA[mf] + ao + ks * 32);
                #pragma unroll
                for (int nf = 0; nf < 8; nf++)
                    mma_f16(acc[mf][nf], a, b[nf][0], b[nf][1]);
            }
        }

        if ((it & 31) == 31) {
            const int nb = (tile0 + (it >> 5)) * 128;
            #pragma unroll
            for (int mf = 0; mf < 2; mf++) {
                const int r0 = warpM * 32 + mf * 16 + gq;
                const int b0 = r0 & 63, b1 = (r0 + 8) & 63;
                #pragma unroll
                for (int nf = 0; nf < 8; nf++) {
                    const int col = nb + warpN * 64 + nf * 8 + 2 * t;
                    if (col < D_) {
                        float2 w  = *(const float2*)(Wa2 + col);
                        float2 q0 = *(const float2*)(qpart + (size_t)b0 * D_ + col);
                        float2 q1 = *(const float2*)(qpart + (size_t)b1 * D_ + col);
                        sacc[mf][0] += fmaxf(acc[mf][nf][0] + q0.x, 0.f) * w.x
                                     + fmaxf(acc[mf][nf][1] + q0.y, 0.f) * w.y;
                        sacc[mf][1] += fmaxf(acc[mf][nf][2] + q1.x, 0.f) * w.x
                                     + fmaxf(acc[mf][nf][3] + q1.y, 0.f) * w.y;
                    }
                    #pragma unroll
                    for (int i = 0; i < 4; i++) acc[mf][nf][i] = 0.f;
                }
            }
        }
    }

    __syncthreads();
    float* red = (float*)dyn;
    #pragma unroll
    for (int mf = 0; mf < 2; mf++) {
        const int r0 = warpM * 32 + mf * 16 + gq;
        red[r0 * 9 + warpN * 4 + t]       = sacc[mf][0];
        red[(r0 + 8) * 9 + warpN * 4 + t] = sacc[mf][1];
    }
    __syncthreads();
    if (tid < 128) {
        float a = 0.f;
        #pragma unroll
        for (int c = 0; c < 8; c++) a += red[tid * 9 + c];
        const int s = blockIdx.x * 2 + (tid >> 6);
        const int b = tid & 63;
        spart[(size_t)blockIdx.y * S_ * B_ + (size_t)s * B_ + b] = a;
    }
}

// ---------------------------------------------------------------------------
// Small kernels
// ---------------------------------------------------------------------------
__global__ void havg_kernel(const float* __restrict__ h, float* __restrict__ havg)
{
    int b = blockIdx.x;
    int e = blockIdx.y * 256 + threadIdx.x;
    float s = 0.f;
    for (int si = 0; si < S_; si++)
        s += h[((size_t)si * B_ + b) * E_ + e];
    havg[(size_t)b * E_ + e] = s * (1.f / (float)S_);
}

__global__ __launch_bounds__(256) void softmax_beta_kernel(
    const float* __restrict__ spart,
    const float* __restrict__ hpart, const float* __restrict__ bh2,
    const float* __restrict__ Wb, const float* __restrict__ bb,
    const float* __restrict__ ba2,
    float* __restrict__ aw_out, float* __restrict__ beta)
{
    const size_t PS = (size_t)B_ * D_;
    int b = blockIdx.x, tid = threadIdx.x;
    __shared__ float sm[256];

    float p = 0.f;
    for (int d = tid; d < D_; d += 256) {
        size_t i = (size_t)b * D_ + d;
        float hv = bh2[d];
        #pragma unroll
        for (int q = 0; q < 6; q++) hv += hpart[q * PS + i];
        p = fmaf(hv, Wb[d], p);
    }
    sm[tid] = p; __syncthreads();
    for (int o = 128; o > 0; o >>= 1) { if (tid < o) sm[tid] += sm[tid + o]; __syncthreads(); }
    if (tid == 0) beta[b] = 1.f / (1.f + expf(-(sm[0] + bb[0])));
    __syncthreads();

    float v = -3.4e38f;
    if (tid < S_) {
        size_t idx = (size_t)tid * B_ + b;
        v = spart[idx] + spart[(size_t)S_ * B_ + idx] + spart[2 * (size_t)S_ * B_ + idx] + ba2[0];
    }
    sm[tid] = v; __syncthreads();
    for (int o = 128; o > 0; o >>= 1) { if (tid < o) sm[tid] = fmaxf(sm[tid], sm[tid + o]); __syncthreads(); }
    float mx = sm[0]; __syncthreads();
    float e = (tid < S_) ? expf(v - mx) : 0.f;
    sm[tid] = e; __syncthreads();
    for (int o = 128; o > 0; o >>= 1) { if (tid < o) sm[tid] += sm[tid + o]; __syncthreads(); }
    float inv = 1.f / sm[0];
    if (tid < S_) aw_out[(size_t)tid * B_ + b] = e * inv;
}

__global__ void ctx_kernel(const float* __restrict__ h, const float* __restrict__ aw,
                           const float* __restrict__ beta, float* __restrict__ ctx)
{
    int b = blockIdx.x;
    int e = blockIdx.y * 256 + threadIdx.x;
    float s = 0.f;
    for (int si = 0; si < S_; si++)
        s = fmaf(aw[(size_t)si * B_ + b], h[((size_t)si * B_ + b) * E_ + e], s);
    ctx[(size_t)b * E_ + e] = s * beta[b];
}

__global__ __launch_bounds__(256) void argmax_kernel(const float* __restrict__ y, int* __restrict__ amax)
{
    int b = blockIdx.x, tid = threadIdx.x;
    float bm = -3.4e38f; int bi = 0;
    for (int i = tid; i < V_; i += 256) {
        float v = y[(size_t)b * V_ + i];
        if (v > bm) { bm = v; bi = i; }
    }
    __shared__ float sv[256];
    __shared__ int si_[256];
    sv[tid] = bm; si_[tid] = bi; __syncthreads();
    for (int o = 128; o > 0; o >>= 1) {
        if (tid < o) {
            if (sv[tid + o] > sv[tid] || (sv[tid + o] == sv[tid] && si_[tid + o] < si_[tid])) {
                sv[tid] = sv[tid + o]; si_[tid] = si_[tid + o];
            }
        }
        __syncthreads();
    }
    if (tid == 0) amax[b] = si_[0];
}

__global__ void xbuild_kernel(const float* __restrict__ emb, const int* __restrict__ Etm1,
                              const float* __restrict__ ctx, float* __restrict__ x)
{
    int b = blockIdx.x;
    int i = blockIdx.y * 256 + threadIdx.x;
    if (i < W_) x[(size_t)b * WE_ + i] = emb[(size_t)Etm1[b] * W_ + i];
    else        x[(size_t)b * WE_ + i] = ctx[(size_t)b * E_ + (i - W_)];
}

// LSTM pointwise: 4+4 gate partial slices, c0 from 6 partial slices + bias.
__global__ void lstm_kernel(const float* __restrict__ gp0, const float* __restrict__ gp1,
                            const float* __restrict__ b_ih, const float* __restrict__ b_hh,
                            const float* __restrict__ cpart, const float* __restrict__ bc2,
                            float* __restrict__ out, float* __restrict__ z)
{
    const size_t P4 = (size_t)B_ * 4 * D_;
    const size_t PS = (size_t)B_ * D_;
    int b = blockIdx.x;
    int d = blockIdx.y * 256 + threadIdx.x;
    if (d >= D_) return;
    const size_t base = (size_t)b * 4 * D_;

    float gi = b_ih[d] + b_hh[d];
    float gf = b_ih[D_ + d] + b_hh[D_ + d];
    float gg = b_ih[2*D_ + d] + b_hh[2*D_ + d];
    float go = b_ih[3*D_ + d] + b_hh[3*D_ + d];
    #pragma unroll
    for (int p = 0; p < 4; p++) {
        gi += gp0[p * P4 + base + d]        + gp1[p * P4 + base + d];
        gf += gp0[p * P4 + base + D_ + d]   + gp1[p * P4 + base + D_ + d];
        gg += gp0[p * P4 + base + 2*D_ + d] + gp1[p * P4 + base + 2*D_ + d];
        go += gp0[p * P4 + base + 3*D_ + d] + gp1[p * P4 + base + 3*D_ + d];
    }
    size_t ci = (size_t)b * D_ + d;
    float c0 = bc2[d];
    #pragma unroll
    for (int p = 0; p < 6; p++) c0 += cpart[p * PS + ci];
    float ig = 1.f / (1.f + expf(-gi));
    float fg = 1.f / (1.f + expf(-gf));
    float gt = tanhf(gg);
    float og = 1.f / (1.f + expf(-go));
    float c = fmaf(fg, c0, ig * gt);
    float ht = og * tanhf(c);
    out[(size_t)B_ * V_ + (size_t)b * D_ + d] = ht;
    out[(size_t)B_ * V_ + (size_t)B_ * D_ + (size_t)b * D_ + d] = c;
    z[(size_t)b * DWE_ + d] = ht;
}

__global__ void zbuild_kernel(const float* __restrict__ emb, const int* __restrict__ amax,
                              const float* __restrict__ ctx, float* __restrict__ z)
{
    int b = blockIdx.x;
    int i = blockIdx.y * 256 + threadIdx.x;
    if (i < W_) z[(size_t)b * DWE_ + D_ + i] = emb[(size_t)amax[b] * W_ + i];
    else        z[(size_t)b * DWE_ + D_ + i] = ctx[(size_t)b * E_ + (i - W_)];
}

// ---------------------------------------------------------------------------
// Launch
// ---------------------------------------------------------------------------
extern "C" void kernel_launch(void* const* d_in, const int* in_sizes, int n_in,
                              void* d_out, int out_size)
{
    const int*   E_tm1 = (const int*)d_in[0];
    const float* y_tm1 = (const float*)d_in[1];
    const float* h     = (const float*)d_in[2];
    const float* emb   = (const float*)d_in[3];
    const float* W_ih  = (const float*)d_in[4];
    const float* b_ih  = (const float*)d_in[5];
    const float* W_hh  = (const float*)d_in[6];
    const float* b_hh  = (const float*)d_in[7];
    const float* W_out = (const float*)d_in[8];
    const float* b_out = (const float*)d_in[9];
    const float* Wh1 = (const float*)d_in[10]; const float* bh1 = (const float*)d_in[11];
    const float* Wh2 = (const float*)d_in[12]; const float* bh2 = (const float*)d_in[13];
    const float* Wc1 = (const float*)d_in[14]; const float* bc1 = (const float*)d_in[15];
    const float* Wc2 = (const float*)d_in[16]; const float* bc2 = (const float*)d_in[17];
    const float* Wa1 = (const float*)d_in[18]; const float* ba1 = (const float*)d_in[19];
    const float* Wa2 = (const float*)d_in[20]; const float* ba2 = (const float*)d_in[21];
    const float* Wb  = (const float*)d_in[22]; const float* bb  = (const float*)d_in[23];
    float* out = (float*)d_out;

    Scratch* s = nullptr;
    cudaGetSymbolAddress((void**)&s, g_s);

    cudaFuncSetAttribute(mma_scores_kernel,
                         cudaFuncAttributeMaxDynamicSharedMemorySize, SC_DYN);

    const int GN_D  = (D_ + 63) / 64;            // 29
    const int GN_4D = (4 * D_ + 127) / 128;      // 57
    const int GN_V  = V_ / 128;                  // 250
    const int CONV_BLK = (S_ * B_ * E_ / 8 + D_ * E_ / 8 + 255) / 256;

    // 0. fp16 preconversion
    conv16_kernel<<<CONV_BLK, 256>>>(h, Wa1, s->h16, s->w16);

    // 1. encoder mean
    havg_kernel<<<dim3(B_, E_ / 256), 256>>>(h, s->havg);

    // 2. init-state layer1 -> partials (KS=6)
    {
        SKJob2 jj;
        jj.j[0] = {s->havg, 1, nullptr, 0, Wh1, E_, E_, D_, s->skpA[0][0]};
        jj.j[1] = {s->havg, 1, nullptr, 0, Wc1, E_, E_, D_, s->skpA[1][0]};
        sk_gemm_kernel<64><<<dim3(GN_D, 2, 6), 256>>>(jj);
    }
    // 3. layer2: A = relu(sum of 6 L1 partials + b1) fused (KS=6)
    {
        SKJob2 jj;
        jj.j[0] = {s->skpA[0][0], 6, bh1, 1, Wh2, D_, D_, D_, s->skpB[0][0]};
        jj.j[1] = {s->skpA[1][0], 6, bc1, 1, Wc2, D_, D_, D_, s->skpB[1][0]};
        sk_gemm_kernel<64><<<dim3(GN_D, 2, 6), 256>>>(jj);
    }
    // 4. qpart partials = (h0 = 6 L2 partials + bh2) @ Wa1[:, :D]^T (KS=6)
    {
        SKJob2 jj;
        jj.j[0] = {s->skpB[0][0], 6, bh2, 0, Wa1, D_, DE_, D_, s->skpA[0][0]};
        jj.j[1] = jj.j[0];
        sk_gemm_kernel<64><<<dim3(GN_D, 1, 6), 256>>>(jj);
    }
    // 5. qpart reduce (6 partials + ba1)
    reduceN_kernel<6><<<(B_ * D_ + 255) / 256, 256>>>(s->skpA[0][0], ba1, s->qpart, D_, B_ * D_);

    // 6. fused scores GEMM
    mma_scores_kernel<<<dim3(S_ / 2, 3), 256, SC_DYN>>>(
        s->h16, s->w16, s->qpart, Wa2, s->spart);

    // 7. argmax
    argmax_kernel<<<B_, 256>>>(y_tm1, s->amax);

    // 8. softmax + beta (h0 virtual from 6 partials)
    float* aw_out = out + (size_t)B_ * V_ + 2 * (size_t)B_ * D_;
    softmax_beta_kernel<<<B_, 256>>>(s->spart, s->skpB[0][0], bh2, Wb, bb, ba2, aw_out, s->beta);

    // 9. context
    ctx_kernel<<<dim3(B_, E_ / 256), 256>>>(h, aw_out, s->beta, s->ctx);

    // 10. LSTM input + gates (KS=4 both jobs)
    xbuild_kernel<<<dim3(B_, WE_ / 256), 256>>>(emb, E_tm1, s->ctx, s->x);
    {
        SKJob2 jj;
        jj.j[0] = {s->x, 1, nullptr, 0, W_ih, WE_, WE_, 4 * D_, s->gp0[0]};
        jj.j[1] = {s->skpB[0][0], 6, bh2, 0, W_hh, D_, D_, 4 * D_, s->gp1[0]};
        sk_gemm_kernel<128><<<dim3(GN_4D, 2, 4), 256>>>(jj);
    }

    // 11. LSTM pointwise (4+4 gate partials; c0 from 6 partials)
    lstm_kernel<<<dim3(B_, (D_ + 255) / 256), 256>>>(
        s->gp0[0], s->gp1[0], b_ih, b_hh, s->skpB[1][0], bc2, out, s->z);

    // 12. z tail
    zbuild_kernel<<<dim3(B_, WE_ / 256), 256>>>(emb, s->amax, s->ctx, s->z);

    // 13. logits (KS=3) + reduce
    {
        SKJob2 jj;
        jj.j[0] = {s->z, 1, nullptr, 0, W_out, DWE_, DWE_, V_, s->lgp[0]};
        jj.j[1] = jj.j[0];
        sk_gemm_kernel<128><<<dim3(GN_V, 1, 3), 256>>>(jj);
    }
    reduceN_kernel<3><<<(B_ * V_ + 255) / 256, 256>>>(s->lgp[0], b_out, out, V_, B_ * V_);
}